// round 5
// baseline (speedup 1.0000x reference)
#include <cuda_runtime.h>
#include <cfloat>
#include <math.h>

// ---------------------------------------------------------------------------
// Problem constants
//   B=2, M=256 -> 512 groups, 64 points/group, KNN=16, CIN=64 (3 xyz + 61 feat)
//   MLPS=[64,128], SUMM=192, CALIB=64, EXP=[256,512], OUT=256
// ---------------------------------------------------------------------------

// Scratch (static device arrays; no runtime allocation)
__device__ float d_x_[512 * 64 * 64];      // input panel  [g][c(64)][n(64)]
__device__ int   d_idx_[512 * 64 * 16];    // knn indices  [g][n][k]
__device__ float d_big_[512 * 256 * 64];   // reused: UT1 (128 rows), UT2 (256 rows), exp1 out (256 rows)
__device__ float d_cat_[512 * 192 * 64];   // concat features [g][c(192)][n]
__device__ float d_c_[512 * 64 * 64];      // cal1 out
__device__ float d_gt_[2 * 512 * 256];     // pooled vector, [b][c(512)][m(256)]
__device__ float d_x1_[2 * 256 * 256];     // after red+bn1
__device__ float d_h_[2 * 256 * 256];      // sc1 out
__device__ float d_ws1_[128 * 64];         // stacked edge weights layer1: [W1 ; W2-W1]
__device__ float d_ws2_[256 * 64];         // stacked edge weights layer2

// ---------------------------------------------------------------------------
// f32x2 packed-FMA helpers (2x fp32 throughput; PTX-only on sm_103a)
// ---------------------------------------------------------------------------
__device__ __forceinline__ unsigned long long pack2(float v) {
    unsigned long long r;
    asm("mov.b64 %0, {%1, %1};" : "=l"(r) : "r"(__float_as_uint(v)));
    return r;
}
__device__ __forceinline__ void ffma2(unsigned long long& d,
                                      unsigned long long a, unsigned long long b) {
    asm("fma.rn.f32x2 %0, %1, %2, %0;" : "+l"(d) : "l"(a), "l"(b));
}
__device__ __forceinline__ float lo2(unsigned long long v) { return __uint_as_float((unsigned)v); }
__device__ __forceinline__ float hi2(unsigned long long v) { return __uint_as_float((unsigned)(v >> 32)); }

// ---------------------------------------------------------------------------
// K0: build stacked EdgeConv weights:  rows [0,C) = W1, rows [C,2C) = W2 - W1
// ---------------------------------------------------------------------------
__global__ void prep_kernel(const float* __restrict__ e1w, const float* __restrict__ e2w) {
    int idx = blockIdx.x * blockDim.x + threadIdx.x;
    if (idx < 128 * 64) {
        int r = idx >> 6, c = idx & 63;
        d_ws1_[idx] = (r < 64) ? e1w[r * 128 + c]
                               : e1w[(r - 64) * 128 + 64 + c] - e1w[(r - 64) * 128 + c];
    }
    int i2 = idx - 128 * 64;
    if (i2 >= 0 && i2 < 256 * 64) {
        int r = i2 >> 6, c = i2 & 63;
        d_ws2_[i2] = (r < 128) ? e2w[r * 128 + c]
                               : e2w[(r - 128) * 128 + 64 + c] - e2w[(r - 128) * 128 + c];
    }
}

// ---------------------------------------------------------------------------
// K1: build input panel d_x (xyz+feats transposed) + 16-NN per point.
// One block per group, 64 threads (one per point).
// ---------------------------------------------------------------------------
__global__ void knn_kernel(const float* __restrict__ xyz, const float* __restrict__ feats) {
    int g = blockIdx.x, t = threadIdx.x;
    __shared__ float px[64], py[64], pz[64], xx[64];
    __shared__ float sbuf[64 * 65];   // feat staging (3904) / padded pd rows (64x65)

    int b3 = (g * 64 + t) * 3;
    float ax = xyz[b3 + 0], ay = xyz[b3 + 1], az = xyz[b3 + 2];
    px[t] = ax; py[t] = ay; pz[t] = az;
    xx[t] = ax * ax + ay * ay + az * az;

    float* xg = d_x_ + (size_t)g * 4096;
    xg[0 * 64 + t] = ax; xg[1 * 64 + t] = ay; xg[2 * 64 + t] = az;

    // stage feats (coalesced) then transpose into d_x channels 3..63
    const float* fg = feats + (size_t)g * 64 * 61;
    for (int i = 0; i < 61; i++) sbuf[i * 64 + t] = fg[i * 64 + t];
    __syncthreads();
    for (int c = 0; c < 61; c++) xg[(3 + c) * 64 + t] = sbuf[t * 61 + c];
    __syncthreads();

    // pd row (padded to 65 -> conflict-free)
    float* row = &sbuf[t * 65];
    float xn = xx[t];
    for (int m = 0; m < 64; m++)
        row[m] = 2.0f * (ax * px[m] + ay * py[m] + az * pz[m]) - xn - xx[m];

    // top-16 by selection (ties -> lowest index, matching jax top_k; only the SET matters)
    int* ig = d_idx_ + (g * 64 + t) * 16;
    for (int k = 0; k < 16; k++) {
        float best = -FLT_MAX; int bi = 0;
        for (int m = 0; m < 64; m++) {
            float v = row[m];
            if (v > best) { best = v; bi = m; }
        }
        ig[k] = bi;
        row[bi] = -FLT_MAX;
    }
}

// ---------------------------------------------------------------------------
// K3/K5: gather-max epilogue of EdgeConv.
// ut layout per group: rows [0,Cout) = U = W1@X, rows [Cout,2Cout) = T = (W2-W1)@X
// out[o,n] = max_k relu( bn( U[o, idx[n,k]] + T[o,n] ) )
// ---------------------------------------------------------------------------
__global__ void gather_kernel(const float* __restrict__ ut,
                              const float* __restrict__ gv, const float* __restrict__ bv,
                              int Cout, int chanOff) {
    int g = blockIdx.x, t = threadIdx.x;   // 256 threads
    __shared__ float Us[128 * 64];
    __shared__ int   sidx[64 * 17];
    const float INVS = rsqrtf(1.0f + 1e-5f);

    const float* utg = ut + (size_t)g * (2 * Cout * 64);
    int tot = Cout * 64;
    for (int i = t; i < tot; i += 256) Us[i] = utg[i];
    const int* idg = d_idx_ + g * 1024;
    for (int i = t; i < 1024; i += 256) {
        int n = i >> 4, k = i & 15;
        sidx[n * 17 + k] = idg[i];
    }
    __syncthreads();

    float* outg = d_cat_ + (size_t)g * 12288 + (size_t)chanOff * 64;
    for (int item = t; item < tot; item += 256) {
        int o = item >> 6, n = item & 63;
        float T = utg[(Cout + o) * 64 + n];
        float s = gv[o] * INVS, b = bv[o];
        const float* Uo = &Us[o * 64];
        const int*   ni = &sidx[n * 17];
        float m = -FLT_MAX;
        #pragma unroll
        for (int k = 0; k < 16; k++) {
            float v = fmaf(Uo[ni[k]] + T, s, b);
            m = fmaxf(m, fmaxf(v, 0.0f));
        }
        outg[o * 64 + n] = m;
    }
}

// ---------------------------------------------------------------------------
// Generic fused GEMM:  out(64o x 64col tile) = epi( W(O x CIN) @ X(CIN x cols) )
// X[c][col] at X + g*imgStride + c*cpi + col.  256 threads, 4x4 accum, f32x2 FMA.
// Epilogues: 0 raw | 1 relu(bn) | 2 sigmoid-gate (cal2) | 3 relu(bn)+max-over-col
//            4 red: relu(bn)*2 ->bn1 | 5 bias+relu | 6 final: bn2(x1 + acc + b)
// ---------------------------------------------------------------------------
template<int EPI>
__global__ void __launch_bounds__(256)
gemm_k(const float* __restrict__ X, int imgStride, int cpi,
       const float* __restrict__ W, int CIN,
       float* out, int outImgStride, int outCpi, int chanOff,
       const float* p0, const float* p1, const float* p2, const float* p3,
       const float* aux) {
    __shared__ __align__(16) float Xs[16][64];
    __shared__ unsigned long long Wsp[64][17];

    const int g = blockIdx.x;
    const int colBase = blockIdx.y << 6;
    const int oBase = blockIdx.z << 6;
    const int t = threadIdx.x;
    const int tn = t & 15, to = t >> 4;

    unsigned long long acc2[4][2];
    #pragma unroll
    for (int i = 0; i < 4; i++) { acc2[i][0] = 0ull; acc2[i][1] = 0ull; }

    const float* Xg = X + (size_t)g * imgStride + colBase;
    const float* Wg = W + (size_t)oBase * CIN;
    const int lxc = t >> 6, lxn = t & 63;
    const int lwo = t >> 4, lwc = t & 15;

    for (int cb = 0; cb < CIN; cb += 16) {
        #pragma unroll
        for (int i = 0; i < 4; i++)
            Xs[lxc + 4 * i][lxn] = Xg[(size_t)(cb + lxc + 4 * i) * cpi + lxn];
        #pragma unroll
        for (int i = 0; i < 4; i++)
            Wsp[lwo + 16 * i][lwc] = pack2(Wg[(size_t)(lwo + 16 * i) * CIN + cb + lwc]);
        __syncthreads();
        #pragma unroll
        for (int c = 0; c < 16; c++) {
            ulonglong2 xv = *reinterpret_cast<const ulonglong2*>(&Xs[c][tn << 2]);
            unsigned long long w0 = Wsp[(to << 2) + 0][c];
            unsigned long long w1 = Wsp[(to << 2) + 1][c];
            unsigned long long w2 = Wsp[(to << 2) + 2][c];
            unsigned long long w3 = Wsp[(to << 2) + 3][c];
            ffma2(acc2[0][0], w0, xv.x); ffma2(acc2[0][1], w0, xv.y);
            ffma2(acc2[1][0], w1, xv.x); ffma2(acc2[1][1], w1, xv.y);
            ffma2(acc2[2][0], w2, xv.x); ffma2(acc2[2][1], w2, xv.y);
            ffma2(acc2[3][0], w3, xv.x); ffma2(acc2[3][1], w3, xv.y);
        }
        __syncthreads();
    }

    float acc[4][4];
    #pragma unroll
    for (int i = 0; i < 4; i++) {
        acc[i][0] = lo2(acc2[i][0]); acc[i][1] = hi2(acc2[i][0]);
        acc[i][2] = lo2(acc2[i][1]); acc[i][3] = hi2(acc2[i][1]);
    }
    const float INVS = rsqrtf(1.0f + 1e-5f);

    if constexpr (EPI == 3) {
        __shared__ float red[64][17];
        #pragma unroll
        for (int i = 0; i < 4; i++) {
            int o = oBase + (to << 2) + i;
            float s = p0[o] * INVS, b = p1[o];
            float m = -FLT_MAX;
            #pragma unroll
            for (int j = 0; j < 4; j++)
                m = fmaxf(m, fmaxf(fmaf(acc[i][j], s, b), 0.0f));
            red[(to << 2) + i][tn] = m;
        }
        __syncthreads();
        if (t < 64) {
            float m = red[t][0];
            #pragma unroll
            for (int q = 1; q < 16; q++) m = fmaxf(m, red[t][q]);
            int bb = g >> 8, mm = g & 255;   // g = b*256 + m
            out[((size_t)bb * 512 + oBase + t) * 256 + mm] = m;
        }
    } else {
        #pragma unroll
        for (int i = 0; i < 4; i++) {
            int o = oBase + (to << 2) + i;
            size_t ob = (size_t)g * outImgStride + (size_t)(chanOff + o) * outCpi
                      + colBase + (tn << 2);
            if constexpr (EPI == 0) {
                #pragma unroll
                for (int j = 0; j < 4; j++) out[ob + j] = acc[i][j];
            } else if constexpr (EPI == 1) {
                float s = p0[o] * INVS, b = p1[o];
                #pragma unroll
                for (int j = 0; j < 4; j++)
                    out[ob + j] = fmaxf(fmaf(acc[i][j], s, b), 0.0f);
            } else if constexpr (EPI == 2) {
                float bb = p0[o];
                #pragma unroll
                for (int j = 0; j < 4; j++) {
                    float v = acc[i][j] + bb;
                    float sg = 1.0f / (1.0f + expf(-v));
                    out[ob + j] = sg * aux[ob + j];
                }
            } else if constexpr (EPI == 4) {
                float sr = p0[o] * INVS, br = p1[o];
                float s1 = p2[o] * INVS, b1 = p3[o];
                #pragma unroll
                for (int j = 0; j < 4; j++) {
                    float r = fmaxf(fmaf(acc[i][j], sr, br), 0.0f);
                    out[ob + j] = fmaf(2.0f * r, s1, b1);
                }
            } else if constexpr (EPI == 5) {
                float bb = p0[o];
                #pragma unroll
                for (int j = 0; j < 4; j++)
                    out[ob + j] = fmaxf(acc[i][j] + bb, 0.0f);
            } else if constexpr (EPI == 6) {
                float bb = p0[o], s2 = p1[o] * INVS, b2 = p2[o];
                #pragma unroll
                for (int j = 0; j < 4; j++) {
                    float v = acc[i][j] + bb + aux[ob + j];
                    out[ob + j] = fmaf(v, s2, b2);
                }
            }
        }
    }
}

// ---------------------------------------------------------------------------
extern "C" void kernel_launch(void* const* d_in, const int* in_sizes, int n_in,
                              void* d_out, int out_size) {
    const float* xyz       = (const float*)d_in[0];
    const float* feats     = (const float*)d_in[1];
    const float* e1_w      = (const float*)d_in[2];
    const float* e1_g      = (const float*)d_in[3];
    const float* e1_b      = (const float*)d_in[4];
    const float* e2_w      = (const float*)d_in[5];
    const float* e2_g      = (const float*)d_in[6];
    const float* e2_b      = (const float*)d_in[7];
    const float* cal1_w    = (const float*)d_in[8];
    const float* cal1_g    = (const float*)d_in[9];
    const float* cal1_b    = (const float*)d_in[10];
    const float* cal2_w    = (const float*)d_in[11];
    const float* cal2_bias = (const float*)d_in[12];
    const float* exp1_w    = (const float*)d_in[13];
    const float* exp1_g    = (const float*)d_in[14];
    const float* exp1_b    = (const float*)d_in[15];
    const float* exp2_w    = (const float*)d_in[16];
    const float* exp2_g    = (const float*)d_in[17];
    const float* exp2_b    = (const float*)d_in[18];
    const float* red_w     = (const float*)d_in[19];
    const float* red_g     = (const float*)d_in[20];
    const float* red_b     = (const float*)d_in[21];
    const float* sc1_w     = (const float*)d_in[22];
    const float* sc1_b     = (const float*)d_in[23];
    const float* sc2_w     = (const float*)d_in[24];
    const float* sc2_b     = (const float*)d_in[25];
    const float* n1_g      = (const float*)d_in[26];
    const float* n1_b      = (const float*)d_in[27];
    const float* n2_g      = (const float*)d_in[28];
    const float* n2_b      = (const float*)d_in[29];

    float *dx, *dbig, *dcat, *dc, *dgt, *dx1, *dh, *dws1, *dws2;
    cudaGetSymbolAddress((void**)&dx,   d_x_);
    cudaGetSymbolAddress((void**)&dbig, d_big_);
    cudaGetSymbolAddress((void**)&dcat, d_cat_);
    cudaGetSymbolAddress((void**)&dc,   d_c_);
    cudaGetSymbolAddress((void**)&dgt,  d_gt_);
    cudaGetSymbolAddress((void**)&dx1,  d_x1_);
    cudaGetSymbolAddress((void**)&dh,   d_h_);
    cudaGetSymbolAddress((void**)&dws1, d_ws1_);
    cudaGetSymbolAddress((void**)&dws2, d_ws2_);

    // K0: stacked edge weights
    prep_kernel<<<96, 256>>>(e1_w, e2_w);
    // K1: input panel + knn
    knn_kernel<<<512, 64>>>(xyz, feats);

    // EdgeConv1: [U;T] = ws1(128x64) @ x  -> gather-max -> d_cat[0:64)
    gemm_k<0><<<dim3(512, 1, 2), 256>>>(dx, 4096, 64, dws1, 64,
                                        dbig, 8192, 64, 0,
                                        nullptr, nullptr, nullptr, nullptr, nullptr);
    gather_kernel<<<512, 256>>>(dbig, e1_g, e1_b, 64, 0);

    // EdgeConv2: [U;T] = ws2(256x64) @ d_cat[0:64)  -> gather-max -> d_cat[64:192)
    gemm_k<0><<<dim3(512, 1, 4), 256>>>(dcat, 12288, 64, dws2, 64,
                                        dbig, 16384, 64, 0,
                                        nullptr, nullptr, nullptr, nullptr, nullptr);
    gather_kernel<<<512, 256>>>(dbig, e2_g, e2_b, 128, 64);

    // calib: c = relu(bn(cal1@x)); x = sigmoid(cal2@c + bias) * x  (gate in-place)
    gemm_k<1><<<dim3(512, 1, 1), 256>>>(dcat, 12288, 64, cal1_w, 192,
                                        dc, 4096, 64, 0,
                                        cal1_g, cal1_b, nullptr, nullptr, nullptr);
    gemm_k<2><<<dim3(512, 1, 3), 256>>>(dc, 4096, 64, cal2_w, 64,
                                        dcat, 12288, 64, 0,
                                        cal2_bias, nullptr, nullptr, nullptr, dcat);

    // exp1: relu(bn(exp1@x))
    gemm_k<1><<<dim3(512, 1, 4), 256>>>(dcat, 12288, 64, exp1_w, 192,
                                        dbig, 16384, 64, 0,
                                        exp1_g, exp1_b, nullptr, nullptr, nullptr);
    // exp2 + max over 64 points, write transposed pooled [b][512][256]
    gemm_k<3><<<dim3(512, 1, 8), 256>>>(dbig, 16384, 64, exp2_w, 256,
                                        dgt, 0, 0, 0,
                                        exp2_g, exp2_b, nullptr, nullptr, nullptr);

    // red: x1 = bn1( 2 * relu(bn(red@pooled)) )
    gemm_k<4><<<dim3(2, 4, 4), 256>>>(dgt, 131072, 256, red_w, 512,
                                      dx1, 65536, 256, 0,
                                      red_g, red_b, n1_g, n1_b, nullptr);
    // sc1: h = relu(sc1@x1 + b)
    gemm_k<5><<<dim3(2, 4, 4), 256>>>(dx1, 65536, 256, sc1_w, 256,
                                      dh, 65536, 256, 0,
                                      sc1_b, nullptr, nullptr, nullptr, nullptr);
    // sc2 + residual + bn2 -> final output (B, 256, 256)
    gemm_k<6><<<dim3(2, 4, 4), 256>>>(dh, 65536, 256, sc2_w, 256,
                                      (float*)d_out, 65536, 256, 0,
                                      sc2_b, n2_g, n2_b, nullptr, dx1);
}